// round 5
// baseline (speedup 1.0000x reference)
#include <cuda_runtime.h>

// NSE_layer: fused NSE residual + BC-mask outputs, 2048x2048 grid.
// Output flat concat: loss (3,3,2046,2046) | mask (1,3,2048,2048) | gbv (2,1,3,2048,2048)
// Structure: [flags (side stream)] || [fused bulk, flag-free] -> [edge_fix rewrites X=0/1/2046/2047 outputs]

#define GNX 2048
#define GNY 2048
#define NNX 2046

__device__ unsigned char g_row_in[GNY];
__device__ unsigned char g_row_out[GNY];

// Warp-per-row flags (runs concurrent with bulk; only edge_fix consumes it).
__global__ __launch_bounds__(256)
void row_flags_kernel(const int* __restrict__ lay) {
    int warp = threadIdx.x >> 5;
    int lane = threadIdx.x & 31;
    int y = blockIdx.x * 8 + warp;
    const int4* row = (const int4*)(lay + (size_t)y * GNX);
    int f = 0;
    #pragma unroll
    for (int i = 0; i < 16; i++) {
        int4 L = __ldg(row + lane + 32 * i);
        f |= ((L.x == 1) | (L.y == 1) | (L.z == 1) | (L.w == 1));
        f |= ((L.x == 3) | (L.y == 3) | (L.z == 3) | (L.w == 3)) << 1;
    }
    f = __reduce_or_sync(0xffffffffu, f);
    if (lane == 0) {
        g_row_in[y]  = (unsigned char)(f & 1);
        g_row_out[y] = (unsigned char)((f >> 1) & 1);
    }
}

// Load one row (6-wide window) of flag-free masked u,v,p. Positions 0..5 = x = xv..xv+5.
__device__ __forceinline__ void load_uvp_row_nf(
    const float* __restrict__ f0, const float* __restrict__ f1,
    const float* __restrict__ f2, const int* __restrict__ lay,
    int r, int xv, bool tail,
    float* u, float* v, float* p, int* lf_out)
{
    size_t off = (size_t)r * GNX + xv;
    float4 ua = __ldg((const float4*)(f0 + off));
    float4 va = __ldg((const float4*)(f1 + off));
    float4 pa = __ldg((const float4*)(f2 + off));
    int4   la = __ldg((const int4*)(lay + off));
    float u4 = 0.f, u5 = 0.f, v4 = 0.f, v5 = 0.f, p4 = 0.f, p5 = 0.f;
    int   l4 = 0, l5 = 0;
    if (!tail) {
        float4 ub = __ldg((const float4*)(f0 + off + 4));
        float4 vb = __ldg((const float4*)(f1 + off + 4));
        float4 pb = __ldg((const float4*)(f2 + off + 4));
        int4   lb = __ldg((const int4*)(lay + off + 4));
        u4 = ub.x; u5 = ub.y; v4 = vb.x; v5 = vb.y; p4 = pb.x; p5 = pb.y;
        l4 = lb.x; l5 = lb.y;
    }
    float uf[6] = {ua.x, ua.y, ua.z, ua.w, u4, u5};
    float vf[6] = {va.x, va.y, va.z, va.w, v4, v5};
    float pf[6] = {pa.x, pa.y, pa.z, pa.w, p4, p5};
    int   lf[6] = {la.x, la.y, la.z, la.w, l4, l5};
    #pragma unroll
    for (int i = 0; i < 6; i++) {
        float m = (lf[i] == 2) ? 0.f : 1.f;
        u[i] = uf[i] * m;
        v[i] = vf[i] * m;
        p[i] = pf[i] * m;
        if (lf_out) lf_out[i] = lf[i];
    }
}

// ---------------- fused bulk kernel: mask+gbv+loss, flag-free ----------------
__global__ __launch_bounds__(256)
void fused_bulk_kernel(const int* __restrict__ lay,
                       const float* __restrict__ f0,
                       const float* __restrict__ f1,
                       const float* __restrict__ f2,
                       float* __restrict__ out_loss,
                       float* __restrict__ out_mask,
                       float* __restrict__ out_gbv)
{
    const size_t NP = (size_t)GNX * GNY;
    const size_t NN = (size_t)NNX * NNX;
    int k = blockIdx.x * 32 + threadIdx.x;        // 0..511 x-chunk
    int Y = blockIdx.y * 8  + threadIdx.y;        // 0..2047
    bool tail = (k == 511);
    int  xv   = 4 * k;
    size_t idx = (size_t)Y * GNX + xv;

    // center-row window (used by both mask and loss)
    float uc[6], vc[6], pc[6];
    int   lc[6];
    load_uvp_row_nf(f0, f1, f2, lay, Y, xv, tail, uc, vc, pc, lc);

    // ---- mask + gbv (flag-free; edge columns fixed later) ----
    {
        float mk0[4], mk1[4], mk2[4], gb[4];
        #pragma unroll
        for (int j = 0; j < 4; j++) {
            int L = lc[j];
            float base = (L == 2) ? 0.f : 1.f;
            float keep = (L > 3) ? 0.f : 1.f;
            float code = (L > 3) ? (float)L : 0.f;
            float m = base * keep + code;
            gb[j] = base; mk0[j] = m; mk1[j] = m; mk2[j] = m;
        }
        float4 mkv = make_float4(mk0[0], mk0[1], mk0[2], mk0[3]);
        float4 gbv = make_float4(gb[0], gb[1], gb[2], gb[3]);
        float4 z   = make_float4(0.f, 0.f, 0.f, 0.f);
        __stcs((float4*)(out_mask + 0 * NP + idx), mkv);
        __stcs((float4*)(out_mask + 1 * NP + idx), mkv);
        __stcs((float4*)(out_mask + 2 * NP + idx), mkv);
        __stcs((float4*)(out_gbv + 0 * NP + idx), gbv);
        __stcs((float4*)(out_gbv + 1 * NP + idx), gbv);
        __stcs((float4*)(out_gbv + 2 * NP + idx), gbv);
        __stcs((float4*)(out_gbv + 3 * NP + idx), z);
        __stcs((float4*)(out_gbv + 4 * NP + idx), z);
        __stcs((float4*)(out_gbv + 5 * NP + idx), z);
    }

    // ---- loss (interior rows only; pixels X = xv+1 .. xv+4) ----
    if (Y >= 1 && Y <= GNY - 2) {
        float un[6], vn[6], pn[6];
        float us[6], vs[6], ps[6];
        load_uvp_row_nf(f0, f1, f2, lay, Y - 1, xv, tail, un, vn, pn, (int*)0);
        load_uvp_row_nf(f0, f1, f2, lay, Y + 1, xv, tail, us, vs, ps, (int*)0);

        const float h     = (float)(0.1 / 2047.0);
        const float inv_h = 1.0f / h;
        const float nu_h2 = 0.05f / (h * h);

        float r0[4], r1[4], r2[4];
        #pragma unroll
        for (int j = 0; j < 4; j++) {
            int   L   = lc[j + 1];
            float Uc  = uc[j + 1], Vc = vc[j + 1];
            float dxu = 0.5f * (uc[j + 2] - uc[j]);
            float dyu = 0.5f * (us[j + 1] - un[j + 1]);
            float dxv = 0.5f * (vc[j + 2] - vc[j]);
            float dyv = 0.5f * (vs[j + 1] - vn[j + 1]);
            float lapu = un[j + 1] + us[j + 1] + uc[j] + uc[j + 2] - 4.0f * Uc;
            float lapv = vn[j + 1] + vs[j + 1] + vc[j] + vc[j + 2] - 4.0f * Vc;
            float cont = dxu * inv_h + dyv * inv_h;

            bool fx  = (L == 4) | (L == 8)  | (L == 11);
            bool bx  = (L == 6) | (L == 9)  | (L == 10);
            bool fy  = (L == 7) | (L == 10) | (L == 11);
            bool by  = (L == 5) | (L == 8)  | (L == 9);
            float dpx = fx ? (pc[j + 2] - pc[j + 1]) : (bx ? (pc[j + 1] - pc[j]) : 0.5f * (pc[j + 2] - pc[j]));
            float dpy = fy ? (pn[j + 1] - pc[j + 1]) : (by ? (pc[j + 1] - ps[j + 1]) : 0.5f * (ps[j + 1] - pn[j + 1]));

            float mu = Uc * dxu * inv_h + Vc * dyu * inv_h + dpx * inv_h - lapu * nu_h2;
            float mv = Uc * dxv * inv_h + Vc * dyv * inv_h + dpy * inv_h - lapv * nu_h2;

            float m = (L == 2) ? 0.f : 1.f;
            r0[j] = m * mu; r1[j] = m * mv; r2[j] = m * cont;
        }

        size_t li = (size_t)(Y - 1) * NNX + xv;     // even -> float2-aligned
        float2 a0 = make_float2(r0[0], r0[1]), b0 = make_float2(r0[2], r0[3]);
        float2 a1 = make_float2(r1[0], r1[1]), b1 = make_float2(r1[2], r1[3]);
        float2 a2 = make_float2(r2[0], r2[1]), b2 = make_float2(r2[2], r2[3]);
        #pragma unroll
        for (int rep = 0; rep < 3; rep++) {
            float* p0 = out_loss + (size_t)(0 * 3 + rep) * NN + li;
            float* p1 = out_loss + (size_t)(1 * 3 + rep) * NN + li;
            float* p2 = out_loss + (size_t)(2 * 3 + rep) * NN + li;
            __stcs((float2*)p0, a0);
            __stcs((float2*)p1, a1);
            __stcs((float2*)p2, a2);
            if (!tail) {
                __stcs((float2*)(p0 + 2), b0);
                __stcs((float2*)(p1 + 2), b1);
                __stcs((float2*)(p2 + 2), b2);
            }
        }
    }
}

// ---------------- edge fix: rewrite all flag-dependent outputs ----------------
// tasks per row: 0 = mask/gbv @ X=0, 1 = mask/gbv @ X=2047, 2 = loss @ X=1, 3 = loss @ X=2046
__global__ __launch_bounds__(256)
void edge_fix_kernel(const int* __restrict__ lay,
                     const float* __restrict__ f0,
                     const float* __restrict__ f1,
                     const float* __restrict__ f2,
                     float* __restrict__ out_loss,
                     float* __restrict__ out_mask,
                     float* __restrict__ out_gbv)
{
    const size_t NP = (size_t)GNX * GNY;
    const size_t NN = (size_t)NNX * NNX;
    int t = blockIdx.x * blockDim.x + threadIdx.x;   // 0..8191
    int task = t & 3;
    int Y = t >> 2;
    if (Y >= GNY) return;

    if (task < 2) {
        int X = task ? (GNX - 1) : 0;
        size_t idx = (size_t)Y * GNX + X;
        int L = __ldg(lay + idx);
        float base = (L == 2) ? 0.f : 1.f;
        float gb0 = base, gb1 = base, gb2 = base, gv0 = 0.f;
        if (X == 0 && g_row_in[Y])        { gb0 = 0.f; gb1 = 0.f; gv0 = 3.f; }
        if (X == GNX - 1 && g_row_out[Y]) { gb2 = 0.f; }
        float keep = (L > 3) ? 0.f : 1.f;
        float code = (L > 3) ? (float)L : 0.f;
        out_mask[0 * NP + idx] = gb0 * keep + code;
        out_mask[1 * NP + idx] = gb1 * keep + code;
        out_mask[2 * NP + idx] = gb2 * keep + code;
        out_gbv[0 * NP + idx] = gb0;
        out_gbv[1 * NP + idx] = gb1;
        out_gbv[2 * NP + idx] = gb2;
        out_gbv[3 * NP + idx] = gv0;
    } else {
        if (Y < 1 || Y > GNY - 2) return;
        int X = (task == 2) ? 1 : (GNX - 2);

        float u[3][3], v[3][3], p[3][3];
        int Lc = 0;
        #pragma unroll
        for (int dy = -1; dy <= 1; dy++) {
            int yy = Y + dy;
            unsigned char rin  = g_row_in[yy];
            unsigned char rout = g_row_out[yy];
            #pragma unroll
            for (int dx = -1; dx <= 1; dx++) {
                int xx = X + dx;
                size_t o = (size_t)yy * GNX + xx;
                int L = __ldg(lay + o);
                float m = (L == 2) ? 0.f : 1.f;
                float uu = __ldg(f0 + o) * m;
                float vv = __ldg(f1 + o) * m;
                float pp = __ldg(f2 + o) * m;
                if (xx == 0 && rin)        { uu = 3.f; vv = 0.f; }
                if (xx == GNX - 1 && rout) { pp = 0.f; }
                u[dy + 1][dx + 1] = uu;
                v[dy + 1][dx + 1] = vv;
                p[dy + 1][dx + 1] = pp;
                if (dy == 0 && dx == 0) Lc = L;
            }
        }

        const float h     = (float)(0.1 / 2047.0);
        const float inv_h = 1.0f / h;
        const float nu_h2 = 0.05f / (h * h);

        float Uc = u[1][1], Vc = v[1][1];
        float dxu = 0.5f * (u[1][2] - u[1][0]);
        float dyu = 0.5f * (u[2][1] - u[0][1]);
        float dxv = 0.5f * (v[1][2] - v[1][0]);
        float dyv = 0.5f * (v[2][1] - v[0][1]);
        float lapu = u[0][1] + u[2][1] + u[1][0] + u[1][2] - 4.0f * Uc;
        float lapv = v[0][1] + v[2][1] + v[1][0] + v[1][2] - 4.0f * Vc;
        float cont = dxu * inv_h + dyv * inv_h;

        int L = Lc;
        bool fx  = (L == 4) | (L == 8)  | (L == 11);
        bool bx  = (L == 6) | (L == 9)  | (L == 10);
        bool fy  = (L == 7) | (L == 10) | (L == 11);
        bool by  = (L == 5) | (L == 8)  | (L == 9);
        float dpx = fx ? (p[1][2] - p[1][1]) : (bx ? (p[1][1] - p[1][0]) : 0.5f * (p[1][2] - p[1][0]));
        float dpy = fy ? (p[0][1] - p[1][1]) : (by ? (p[1][1] - p[2][1]) : 0.5f * (p[2][1] - p[0][1]));

        float mu = Uc * dxu * inv_h + Vc * dyu * inv_h + dpx * inv_h - lapu * nu_h2;
        float mv = Uc * dxv * inv_h + Vc * dyv * inv_h + dpy * inv_h - lapv * nu_h2;

        float m = (L == 2) ? 0.f : 1.f;
        float r0 = m * mu, r1 = m * mv, r2 = m * cont;

        size_t li = (size_t)(Y - 1) * NNX + (X - 1);
        #pragma unroll
        for (int rep = 0; rep < 3; rep++) {
            out_loss[(size_t)(0 * 3 + rep) * NN + li] = r0;
            out_loss[(size_t)(1 * 3 + rep) * NN + li] = r1;
            out_loss[(size_t)(2 * 3 + rep) * NN + li] = r2;
        }
    }
}

extern "C" void kernel_launch(void* const* d_in, const int* in_sizes, int n_in,
                              void* d_out, int out_size) {
    const int*   layout = (const int*)d_in[0];
    const float* flow   = (const float*)d_in[1];
    const size_t NP = (size_t)GNX * GNY;
    const size_t NN = (size_t)NNX * NNX;

    const int*   lay = layout + NP;        // layout[0,1]
    const float* f0  = flow;
    const float* f1  = flow + NP;
    const float* f2  = flow + 2 * NP;

    float* out      = (float*)d_out;
    float* out_loss = out;
    float* out_mask = out_loss + 9 * NN;
    float* out_gbv  = out_mask + 3 * NP;

    static cudaStream_t s_side = 0;
    static cudaEvent_t  ev_fork = 0, ev_join = 0;
    if (s_side == 0) {
        cudaStreamCreateWithFlags(&s_side, cudaStreamNonBlocking);
        cudaEventCreateWithFlags(&ev_fork, cudaEventDisableTiming);
        cudaEventCreateWithFlags(&ev_join, cudaEventDisableTiming);
    }

    // fork: flags on side stream, concurrent with the flag-free bulk kernel
    cudaEventRecord(ev_fork, 0);
    cudaStreamWaitEvent(s_side, ev_fork, 0);
    row_flags_kernel<<<GNY / 8, 256, 0, s_side>>>(lay);
    cudaEventRecord(ev_join, s_side);

    dim3 block(32, 8);
    fused_bulk_kernel<<<dim3(16, 256), block>>>(lay, f0, f1, f2, out_loss, out_mask, out_gbv);

    // join, then fix the flag-dependent edge outputs
    cudaStreamWaitEvent(0, ev_join, 0);
    edge_fix_kernel<<<32, 256>>>(lay, f0, f1, f2, out_loss, out_mask, out_gbv);
}